// round 15
// baseline (speedup 1.0000x reference)
#include <cuda_runtime.h>

#define Bb 256
#define Tt 250
#define Ii 700
#define Nn 2048
#define Oo 20
#define KC 512   // Eigen k-panel, l1/kdiv = 32768/64 variant (no ksub): gemm1 512|188, rec 4x512

// Scratch (device globals: allocation-free rule)
__device__ float g_IN[(size_t)Tt * Bb * Nn];   // [T][B][N] input currents (x@W1 + b1)
__device__ float g_mem[Bb * Nn];               // LSM membrane [B][N]
__device__ float g_spkf[2][Bb * Nn];           // spike matrices as float, ping-pong
__device__ float g_memout[Bb * Oo];            // output membrane [B][O]

// ---------------------------------------------------------------------------
__global__ void zero_init() {
    int idx = blockIdx.x * blockDim.x + threadIdx.x;
    int stride = gridDim.x * blockDim.x;
    for (int i = idx; i < Bb * Nn; i += stride) { g_mem[i] = 0.f; g_spkf[0][i] = 0.f; }
    for (int i = idx; i < Bb * Oo; i += stride) g_memout[i] = 0.f;
}

// ---------------------------------------------------------------------------
// GEMM1: IN[t][b][n] = data[b][t][:] @ W1[:, n] + b1[n]
// kc=512 panels: ascending-k FMA chain within [0,512) and [512,700),
// one rounded C += panel add at k=512. Bias added as one separate
// rounded add (HLO add(dot, b1)).
__global__ __launch_bounds__(256) void gemm1(const float* __restrict__ A,
                                             const float* __restrict__ W1,
                                             const float* __restrict__ b1) {
    __shared__ float As[8][128];   // transposed A tile
    __shared__ float Bs[8][128];
    const int tid  = threadIdx.x;
    const int col0 = blockIdx.x * 128;
    const int row0 = blockIdx.y * 128;
    const int aRow = tid >> 1;
    const int aCol = (tid & 1) * 4;
    const int bRow = tid >> 5;
    const int bCol = (tid & 31) * 4;
    const int tx = tid & 15, ty = tid >> 4;

    float tot[8][8], acc[8][8];
#pragma unroll
    for (int i = 0; i < 8; i++)
#pragma unroll
        for (int j = 0; j < 8; j++) { tot[i][j] = 0.f; acc[i][j] = 0.f; }

#pragma unroll 1
    for (int k0 = 0; k0 < Ii; k0 += 8) {
        float4 av = make_float4(0.f, 0.f, 0.f, 0.f);
        if (k0 + aCol < Ii)  // Ii % 4 == 0 so a full float4 stays in-bounds
            av = *(const float4*)(A + (size_t)(row0 + aRow) * Ii + k0 + aCol);
        As[aCol + 0][aRow] = av.x;
        As[aCol + 1][aRow] = av.y;
        As[aCol + 2][aRow] = av.z;
        As[aCol + 3][aRow] = av.w;

        float4 bv = make_float4(0.f, 0.f, 0.f, 0.f);
        if (k0 + bRow < Ii)
            bv = *(const float4*)(W1 + (size_t)(k0 + bRow) * Nn + col0 + bCol);
        *(float4*)&Bs[bRow][bCol] = bv;
        __syncthreads();

#pragma unroll
        for (int k = 0; k < 8; k++) {
            float4 a0 = *(const float4*)&As[k][ty * 8];
            float4 a1 = *(const float4*)&As[k][ty * 8 + 4];
            float4 c0 = *(const float4*)&Bs[k][tx * 8];
            float4 c1 = *(const float4*)&Bs[k][tx * 8 + 4];
            float ra[8] = {a0.x, a0.y, a0.z, a0.w, a1.x, a1.y, a1.z, a1.w};
            float rb[8] = {c0.x, c0.y, c0.z, c0.w, c1.x, c1.y, c1.z, c1.w};
#pragma unroll
            for (int i = 0; i < 8; i++)
#pragma unroll
                for (int j = 0; j < 8; j++)
                    acc[i][j] = __fmaf_rn(ra[i], rb[j], acc[i][j]);
        }
        __syncthreads();

        if (((k0 + 8) % KC) == 0) {   // panel boundary at k=512: C += panel
#pragma unroll
            for (int i = 0; i < 8; i++)
#pragma unroll
                for (int j = 0; j < 8; j++) {
                    tot[i][j] = __fadd_rn(tot[i][j], acc[i][j]);
                    acc[i][j] = 0.f;
                }
        }
    }
    // final fold: C += tail panel [512,700)
#pragma unroll
    for (int i = 0; i < 8; i++)
#pragma unroll
        for (int j = 0; j < 8; j++)
            tot[i][j] = __fadd_rn(tot[i][j], acc[i][j]);

    float bias[8];
#pragma unroll
    for (int j = 0; j < 8; j++) bias[j] = b1[col0 + tx * 8 + j];

#pragma unroll
    for (int i = 0; i < 8; i++) {
        int r  = row0 + ty * 8 + i;
        int bi = r / Tt;
        int tt = r - bi * Tt;
        float* c = g_IN + ((size_t)tt * Bb + bi) * Nn + col0 + tx * 8;
#pragma unroll
        for (int j = 0; j < 8; j++)
            c[j] = __fadd_rn(tot[i][j], bias[j]);   // in_curr = dot + b1
    }
}

// ---------------------------------------------------------------------------
// Recurrent step, fused: REC = spk_prev @ V with kc=512 panels: ascending
// FMA chain within each, rounded C += panel at k=512,1024,1536,2048 (exact
// 4-panel cover, no tail). Then CONTRACTED RLeaky update:
//   m' = ((fma(0.9, m, ic) + rec) + bV) - reset
// Tile 64 samples x 64 neurons, grid (32, 4) = 128 CTAs, 128 threads,
// microtile 4 rows x 8 cols.
__global__ __launch_bounds__(128) void rec_step(int t, int pp,
                                                const float* __restrict__ V,
                                                const float* __restrict__ bV) {
    __shared__ float As[8][64];   // [kk][sample-row]
    __shared__ float Bs[8][64];   // [kk][neuron-col]
    const int tid = threadIdx.x;
    const int n0  = blockIdx.x * 64;
    const int b0  = blockIdx.y * 64;
    const float* __restrict__ S = g_spkf[pp];

    const int rg = tid >> 3;          // 0..15, rows rg*4..+3
    const int cg = tid & 7;           // 0..7,  cols cg*8..+7

    const int lr  = tid >> 1;         // 0..63 : A-load row
    const int lk4 = (tid & 1) * 4;    // 0 or 4: A-load k offset
    const int lkb = tid >> 4;         // 0..7  : B-load k row
    const int lc4 = (tid & 15) * 4;   // 0..60 : B-load col offset

    float tot[4][8], acc[4][8];
#pragma unroll
    for (int i = 0; i < 4; i++)
#pragma unroll
        for (int j = 0; j < 8; j++) { tot[i][j] = 0.f; acc[i][j] = 0.f; }

#pragma unroll 1
    for (int k0 = 0; k0 < Nn; k0 += 8) {
        float4 a = *(const float4*)(S + (size_t)(b0 + lr) * Nn + k0 + lk4);
        As[lk4 + 0][lr] = a.x;
        As[lk4 + 1][lr] = a.y;
        As[lk4 + 2][lr] = a.z;
        As[lk4 + 3][lr] = a.w;
        float4 v4 = *(const float4*)(V + (size_t)(k0 + lkb) * Nn + n0 + lc4);
        *(float4*)&Bs[lkb][lc4] = v4;
        __syncthreads();

#pragma unroll
        for (int kk = 0; kk < 8; kk++) {
            float4 av  = *(const float4*)&As[kk][rg * 4];
            float4 bv0 = *(const float4*)&Bs[kk][cg * 8];
            float4 bv1 = *(const float4*)&Bs[kk][cg * 8 + 4];
            float ra[4] = {av.x, av.y, av.z, av.w};
            float rb[8] = {bv0.x, bv0.y, bv0.z, bv0.w, bv1.x, bv1.y, bv1.z, bv1.w};
#pragma unroll
            for (int i = 0; i < 4; i++)
#pragma unroll
                for (int j = 0; j < 8; j++)
                    acc[i][j] = __fmaf_rn(ra[i], rb[j], acc[i][j]);
        }
        __syncthreads();

        if (((k0 + 8) % KC) == 0) {   // folds at k=512,1024,1536,2048
#pragma unroll
            for (int i = 0; i < 4; i++)
#pragma unroll
                for (int j = 0; j < 8; j++) {
                    tot[i][j] = __fadd_rn(tot[i][j], acc[i][j]);
                    acc[i][j] = 0.f;
                }
        }
    }

    // Epilogue: acc == 0 here (fold fired at k=2048); CONTRACTED update.
    float bvv[8];
#pragma unroll
    for (int j = 0; j < 8; j++) bvv[j] = bV[n0 + cg * 8 + j];
    float* __restrict__ Snext = g_spkf[pp ^ 1];

#pragma unroll
    for (int i = 0; i < 4; i++) {
        int b = b0 + rg * 4 + i;
        size_t base = (size_t)b * Nn + n0 + cg * 8;
        const float* icp = g_IN + (size_t)t * Bb * Nn + base;
#pragma unroll
        for (int j = 0; j < 8; j++) {
            float rec = __fadd_rn(tot[i][j], acc[i][j]);   // exact: acc==0
            float m = g_mem[base + j];
            float r = (m > 1.0f) ? 1.0f : 0.0f;            // reset from previous mem
            m = __fmaf_rn(0.9f, m, icp[j]);                // fma: beta*mem + in_curr
            m = __fadd_rn(m, rec);
            m = __fadd_rn(m, bvv[j]);
            m = __fsub_rn(m, r);
            g_mem[base + j]  = m;
            Snext[base + j]  = (m > 1.0f) ? 1.0f : 0.0f;
        }
    }
}

// ---------------------------------------------------------------------------
// Output step: out_curr[b,o] = sum_k spk[b,k]*W2[k,o] with kc=512 panel
// folding, oc = dot + b2, CONTRACTED LIF update.
// grid = B, block = 32 (threads o < 20 active).
__global__ __launch_bounds__(32) void out_step(int t, int pc,
                                               const float* __restrict__ W2,
                                               const float* __restrict__ b2,
                                               float* __restrict__ out) {
    const int b = blockIdx.x;
    const int o = threadIdx.x;
    if (o >= Oo) return;

    const float* __restrict__ s = g_spkf[pc] + (size_t)b * Nn;
    float tot = 0.f, acc = 0.f;
#pragma unroll 8
    for (int k = 0; k < Nn; k++) {
        acc = __fmaf_rn(s[k], W2[(size_t)k * Oo + o], acc);
        if (((k + 1) % KC) == 0) { tot = __fadd_rn(tot, acc); acc = 0.f; }
    }
    tot = __fadd_rn(tot, acc);                   // exact 0-add (folded at 2048)

    float oc = __fadd_rn(tot, b2[o]);
    float m  = g_memout[b * Oo + o];
    float r  = (m > 1.0f) ? 1.0f : 0.0f;
    m = __fmaf_rn(0.8f, m, oc);                  // fma: beta*mem + out_curr
    m = __fsub_rn(m, r);
    g_memout[b * Oo + o] = m;

    float sp = (m > 1.0f) ? 1.0f : 0.0f;
    size_t o1 = ((size_t)t * Bb + b) * Oo + o;
    out[o1] = sp;                                  // spk_rec
    out[(size_t)Tt * Bb * Oo + o1] = m;            // mem_rec
}

// ---------------------------------------------------------------------------
extern "C" void kernel_launch(void* const* d_in, const int* in_sizes, int n_in,
                              void* d_out, int out_size) {
    const float* data = (const float*)d_in[0];  // [B,T,I]
    const float* W1   = (const float*)d_in[1];  // [I,N]
    const float* b1   = (const float*)d_in[2];  // [N]
    const float* V    = (const float*)d_in[3];  // [N,N]
    const float* bV   = (const float*)d_in[4];  // [N]
    const float* W2   = (const float*)d_in[5];  // [N,O]
    const float* b2   = (const float*)d_in[6];  // [O]
    float* out = (float*)d_out;

    zero_init<<<256, 256>>>();

    dim3 g1(Nn / 128, (Bb * Tt) / 128);  // (16, 500)
    gemm1<<<g1, 256>>>(data, W1, b1);

    for (int t = 0; t < Tt; ++t) {
        int pp = t & 1;
        rec_step<<<dim3(Nn / 64, Bb / 64), 128>>>(t, pp, V, bV);
        out_step<<<Bb, 32>>>(t, pp ^ 1, W2, b2, out);
    }
}

// round 16
// speedup vs baseline: 1.6912x; 1.6912x over previous
#include <cuda_runtime.h>

#define Bb 256
#define Tt 250
#define Ii 700
#define Nn 2048
#define Oo 20
#define KC 512   // reference k-panel: ascending FMA chains, rounded folds at 512 (VERIFIED R14)

// Scratch (device globals: allocation-free rule)
__device__ float g_IN[(size_t)Tt * Bb * Nn];   // [T][B][N] input currents (x@W1 + b1)
__device__ float g_mem[Bb * Nn];               // LSM membrane [B][N]
__device__ float g_spkf[2][Bb * Nn];           // spike matrices as float, ping-pong
__device__ float g_memout[Bb * Oo];            // output membrane [B][O]
__device__ float g_part[4 * (size_t)Bb * Nn];  // rec GEMM panel partials [panel][B][N]

// ---------------------------------------------------------------------------
__global__ void zero_init() {
    int idx = blockIdx.x * blockDim.x + threadIdx.x;
    int stride = gridDim.x * blockDim.x;
    for (int i = idx; i < Bb * Nn; i += stride) { g_mem[i] = 0.f; g_spkf[0][i] = 0.f; }
    for (int i = idx; i < Bb * Oo; i += stride) g_memout[i] = 0.f;
}

// ---------------------------------------------------------------------------
// GEMM1: IN[t][b][n] = data[b][t][:] @ W1[:, n] + b1[n]
// kc=512 panels: ascending-k FMA chain within [0,512) and [512,700),
// one rounded C += panel add at k=512. Bias: one separate rounded add.
// (UNCHANGED from passing R14 kernel.)
__global__ __launch_bounds__(256) void gemm1(const float* __restrict__ A,
                                             const float* __restrict__ W1,
                                             const float* __restrict__ b1) {
    __shared__ float As[8][128];   // transposed A tile
    __shared__ float Bs[8][128];
    const int tid  = threadIdx.x;
    const int col0 = blockIdx.x * 128;
    const int row0 = blockIdx.y * 128;
    const int aRow = tid >> 1;
    const int aCol = (tid & 1) * 4;
    const int bRow = tid >> 5;
    const int bCol = (tid & 31) * 4;
    const int tx = tid & 15, ty = tid >> 4;

    float tot[8][8], acc[8][8];
#pragma unroll
    for (int i = 0; i < 8; i++)
#pragma unroll
        for (int j = 0; j < 8; j++) { tot[i][j] = 0.f; acc[i][j] = 0.f; }

#pragma unroll 1
    for (int k0 = 0; k0 < Ii; k0 += 8) {
        float4 av = make_float4(0.f, 0.f, 0.f, 0.f);
        if (k0 + aCol < Ii)  // Ii % 4 == 0 so a full float4 stays in-bounds
            av = *(const float4*)(A + (size_t)(row0 + aRow) * Ii + k0 + aCol);
        As[aCol + 0][aRow] = av.x;
        As[aCol + 1][aRow] = av.y;
        As[aCol + 2][aRow] = av.z;
        As[aCol + 3][aRow] = av.w;

        float4 bv = make_float4(0.f, 0.f, 0.f, 0.f);
        if (k0 + bRow < Ii)
            bv = *(const float4*)(W1 + (size_t)(k0 + bRow) * Nn + col0 + bCol);
        *(float4*)&Bs[bRow][bCol] = bv;
        __syncthreads();

#pragma unroll
        for (int k = 0; k < 8; k++) {
            float4 a0 = *(const float4*)&As[k][ty * 8];
            float4 a1 = *(const float4*)&As[k][ty * 8 + 4];
            float4 c0 = *(const float4*)&Bs[k][tx * 8];
            float4 c1 = *(const float4*)&Bs[k][tx * 8 + 4];
            float ra[8] = {a0.x, a0.y, a0.z, a0.w, a1.x, a1.y, a1.z, a1.w};
            float rb[8] = {c0.x, c0.y, c0.z, c0.w, c1.x, c1.y, c1.z, c1.w};
#pragma unroll
            for (int i = 0; i < 8; i++)
#pragma unroll
                for (int j = 0; j < 8; j++)
                    acc[i][j] = __fmaf_rn(ra[i], rb[j], acc[i][j]);
        }
        __syncthreads();

        if (((k0 + 8) % KC) == 0) {   // panel boundary at k=512: C += panel
#pragma unroll
            for (int i = 0; i < 8; i++)
#pragma unroll
                for (int j = 0; j < 8; j++) {
                    tot[i][j] = __fadd_rn(tot[i][j], acc[i][j]);
                    acc[i][j] = 0.f;
                }
        }
    }
    // final fold: C += tail panel [512,700)
#pragma unroll
    for (int i = 0; i < 8; i++)
#pragma unroll
        for (int j = 0; j < 8; j++)
            tot[i][j] = __fadd_rn(tot[i][j], acc[i][j]);

    float bias[8];
#pragma unroll
    for (int j = 0; j < 8; j++) bias[j] = b1[col0 + tx * 8 + j];

#pragma unroll
    for (int i = 0; i < 8; i++) {
        int r  = row0 + ty * 8 + i;
        int bi = r / Tt;
        int tt = r - bi * Tt;
        float* c = g_IN + ((size_t)tt * Bb + bi) * Nn + col0 + tx * 8;
#pragma unroll
        for (int j = 0; j < 8; j++)
            c[j] = __fadd_rn(tot[i][j], bias[j]);   // in_curr = dot + b1
    }
}

// ---------------------------------------------------------------------------
// rec_gemm: one 512-wide k-panel of REC = spk_prev @ V per CTA.
// grid (32 n-tiles, 4 b-tiles, 4 panels) = 512 CTAs; identical per-element
// ascending FMA chain as the fused version, just executed in parallel CTAs.
// Partials land in g_part[panel]; rec_update folds them IN ORDER.
__global__ __launch_bounds__(128) void rec_gemm(int pp, const float* __restrict__ V) {
    __shared__ float As[8][64];   // [kk][sample-row]
    __shared__ float Bs[8][64];   // [kk][neuron-col]
    const int tid  = threadIdx.x;
    const int n0   = blockIdx.x * 64;
    const int b0   = blockIdx.y * 64;
    const int kbeg = blockIdx.z * KC;
    const float* __restrict__ S = g_spkf[pp];

    const int rg = tid >> 3;          // 0..15, rows rg*4..+3
    const int cg = tid & 7;           // 0..7,  cols cg*8..+7

    const int lr  = tid >> 1;         // 0..63 : A-load row
    const int lk4 = (tid & 1) * 4;    // 0 or 4: A-load k offset
    const int lkb = tid >> 4;         // 0..7  : B-load k row
    const int lc4 = (tid & 15) * 4;   // 0..60 : B-load col offset

    float acc[4][8];
#pragma unroll
    for (int i = 0; i < 4; i++)
#pragma unroll
        for (int j = 0; j < 8; j++) acc[i][j] = 0.f;

#pragma unroll 1
    for (int k0 = kbeg; k0 < kbeg + KC; k0 += 8) {
        float4 a = *(const float4*)(S + (size_t)(b0 + lr) * Nn + k0 + lk4);
        As[lk4 + 0][lr] = a.x;
        As[lk4 + 1][lr] = a.y;
        As[lk4 + 2][lr] = a.z;
        As[lk4 + 3][lr] = a.w;
        float4 v4 = *(const float4*)(V + (size_t)(k0 + lkb) * Nn + n0 + lc4);
        *(float4*)&Bs[lkb][lc4] = v4;
        __syncthreads();

#pragma unroll
        for (int kk = 0; kk < 8; kk++) {
            float4 av  = *(const float4*)&As[kk][rg * 4];
            float4 bv0 = *(const float4*)&Bs[kk][cg * 8];
            float4 bv1 = *(const float4*)&Bs[kk][cg * 8 + 4];
            float ra[4] = {av.x, av.y, av.z, av.w};
            float rb[8] = {bv0.x, bv0.y, bv0.z, bv0.w, bv1.x, bv1.y, bv1.z, bv1.w};
#pragma unroll
            for (int i = 0; i < 4; i++)
#pragma unroll
                for (int j = 0; j < 8; j++)
                    acc[i][j] = __fmaf_rn(ra[i], rb[j], acc[i][j]);
        }
        __syncthreads();
    }

    float* __restrict__ P = g_part + (size_t)blockIdx.z * (Bb * Nn);
#pragma unroll
    for (int i = 0; i < 4; i++) {
        size_t base = (size_t)(b0 + rg * 4 + i) * Nn + n0 + cg * 8;
        *(float4*)(P + base)     = make_float4(acc[i][0], acc[i][1], acc[i][2], acc[i][3]);
        *(float4*)(P + base + 4) = make_float4(acc[i][4], acc[i][5], acc[i][6], acc[i][7]);
    }
}

// ---------------------------------------------------------------------------
// rec_update: fold panel partials in ASCENDING order (tot=0; tot+=P0..P3 —
// identical rounded adds to the fused fold), then CONTRACTED RLeaky update:
//   m' = ((fma(0.9, m, ic) + rec) + bV) - reset
// One float4 per thread; grid 512 x 256 covers Bb*Nn.
__global__ __launch_bounds__(256) void rec_update(int t, int pp,
                                                  const float* __restrict__ bV) {
    const size_t e = ((size_t)blockIdx.x * 256 + threadIdx.x) * 4;
    const int n = (int)(e & (Nn - 1));
    const float4 p0 = *(const float4*)(g_part + e);
    const float4 p1 = *(const float4*)(g_part + (size_t)(Bb * Nn) + e);
    const float4 p2 = *(const float4*)(g_part + 2 * (size_t)(Bb * Nn) + e);
    const float4 p3 = *(const float4*)(g_part + 3 * (size_t)(Bb * Nn) + e);
    float4 m4 = *(float4*)(g_mem + e);
    const float4 ic = *(const float4*)(g_IN + (size_t)t * Bb * Nn + e);
    const float4 bv = *(const float4*)(bV + n);
    float4 s4;

#define REC_UP(c)                                                              \
    {                                                                          \
        float tot = 0.f;                                                       \
        tot = __fadd_rn(tot, p0.c);                                            \
        tot = __fadd_rn(tot, p1.c);                                            \
        tot = __fadd_rn(tot, p2.c);                                            \
        tot = __fadd_rn(tot, p3.c);                                            \
        float m = m4.c;                                                        \
        float r = (m > 1.0f) ? 1.0f : 0.0f;                                    \
        m = __fmaf_rn(0.9f, m, ic.c);                                          \
        m = __fadd_rn(m, tot);                                                 \
        m = __fadd_rn(m, bv.c);                                                \
        m = __fsub_rn(m, r);                                                   \
        m4.c = m;                                                              \
        s4.c = (m > 1.0f) ? 1.0f : 0.0f;                                       \
    }
    REC_UP(x) REC_UP(y) REC_UP(z) REC_UP(w)
#undef REC_UP

    *(float4*)(g_mem + e) = m4;
    *(float4*)(g_spkf[pp ^ 1] + e) = s4;
}

// ---------------------------------------------------------------------------
// out_step: panel-parallel. Warp s owns k-panel [s*512,(s+1)*512): lane o
// runs the ascending FMA chain (sp[k] warp-uniform broadcast, W2 coalesced).
// Panels folded in ascending order via smem — identical rounding to fused.
// Then oc = dot + b2, CONTRACTED LIF, outputs.
__global__ __launch_bounds__(128) void out_step(int t, int pc,
                                                const float* __restrict__ W2,
                                                const float* __restrict__ b2,
                                                float* __restrict__ out) {
    __shared__ float sred[4][32];
    const int b = blockIdx.x;
    const int s = threadIdx.x >> 5;   // panel = warp id
    const int o = threadIdx.x & 31;

    float p = 0.f;
    if (o < Oo) {
        const float* __restrict__ sp = g_spkf[pc] + (size_t)b * Nn + s * KC;
        const float* __restrict__ w  = W2 + (size_t)(s * KC) * Oo + o;
#pragma unroll 8
        for (int k = 0; k < KC; k++)
            p = __fmaf_rn(sp[k], w[(size_t)k * Oo], p);
    }
    sred[s][o] = p;
    __syncthreads();

    if (threadIdx.x < 32 && o < Oo) {
        float tot = 0.f;
        tot = __fadd_rn(tot, sred[0][o]);
        tot = __fadd_rn(tot, sred[1][o]);
        tot = __fadd_rn(tot, sred[2][o]);
        tot = __fadd_rn(tot, sred[3][o]);

        float oc = __fadd_rn(tot, b2[o]);
        float m  = g_memout[b * Oo + o];
        float r  = (m > 1.0f) ? 1.0f : 0.0f;
        m = __fmaf_rn(0.8f, m, oc);                  // fma: beta*mem + out_curr
        m = __fsub_rn(m, r);
        g_memout[b * Oo + o] = m;

        float sp_v = (m > 1.0f) ? 1.0f : 0.0f;
        size_t o1 = ((size_t)t * Bb + b) * Oo + o;
        out[o1] = sp_v;                                // spk_rec
        out[(size_t)Tt * Bb * Oo + o1] = m;            // mem_rec
    }
}

// ---------------------------------------------------------------------------
extern "C" void kernel_launch(void* const* d_in, const int* in_sizes, int n_in,
                              void* d_out, int out_size) {
    const float* data = (const float*)d_in[0];  // [B,T,I]
    const float* W1   = (const float*)d_in[1];  // [I,N]
    const float* b1   = (const float*)d_in[2];  // [N]
    const float* V    = (const float*)d_in[3];  // [N,N]
    const float* bV   = (const float*)d_in[4];  // [N]
    const float* W2   = (const float*)d_in[5];  // [N,O]
    const float* b2   = (const float*)d_in[6];  // [O]
    float* out = (float*)d_out;

    zero_init<<<256, 256>>>();

    dim3 g1(Nn / 128, (Bb * Tt) / 128);  // (16, 500)
    gemm1<<<g1, 256>>>(data, W1, b1);

    for (int t = 0; t < Tt; ++t) {
        int pp = t & 1;
        rec_gemm<<<dim3(Nn / 64, Bb / 64, 4), 128>>>(pp, V);
        rec_update<<<512, 256>>>(t, pp, bV);
        out_step<<<Bb, 128>>>(t, pp ^ 1, W2, b2, out);
    }
}

// round 17
// speedup vs baseline: 1.6961x; 1.0029x over previous
#include <cuda_runtime.h>

#define Bb 256
#define Tt 250
#define Ii 700
#define Nn 2048
#define Oo 20
#define KC 512   // reference k-panel: ascending FMA chains, rounded folds at 512 (VERIFIED R14)

// Scratch (device globals: allocation-free rule)
__device__ float g_IN[(size_t)Tt * Bb * Nn];   // [T][B][N] input currents (x@W1 + b1)
__device__ float g_mem[Bb * Nn];               // LSM membrane [B][N]
__device__ float g_spkf[2][Bb * Nn];           // spike matrices as float, ping-pong
__device__ float g_memout[Bb * Oo];            // output membrane [B][O]
__device__ float g_part[4 * (size_t)Bb * Nn];  // rec GEMM panel partials [panel][B][N]

// ---------------------------------------------------------------------------
__global__ void zero_init() {
    int idx = blockIdx.x * blockDim.x + threadIdx.x;
    int stride = gridDim.x * blockDim.x;
    for (int i = idx; i < Bb * Nn; i += stride) { g_mem[i] = 0.f; g_spkf[0][i] = 0.f; }
    for (int i = idx; i < Bb * Oo; i += stride) g_memout[i] = 0.f;
}

// ---------------------------------------------------------------------------
// GEMM1: IN[t][b][n] = data[b][t][:] @ W1[:, n] + b1[n]
// kc=512 panels: ascending-k FMA chain within [0,512) and [512,700),
// one rounded C += panel add at k=512. Bias: one separate rounded add.
// (UNCHANGED from passing R14/R15 kernel.)
__global__ __launch_bounds__(256) void gemm1(const float* __restrict__ A,
                                             const float* __restrict__ W1,
                                             const float* __restrict__ b1) {
    __shared__ float As[8][128];   // transposed A tile
    __shared__ float Bs[8][128];
    const int tid  = threadIdx.x;
    const int col0 = blockIdx.x * 128;
    const int row0 = blockIdx.y * 128;
    const int aRow = tid >> 1;
    const int aCol = (tid & 1) * 4;
    const int bRow = tid >> 5;
    const int bCol = (tid & 31) * 4;
    const int tx = tid & 15, ty = tid >> 4;

    float tot[8][8], acc[8][8];
#pragma unroll
    for (int i = 0; i < 8; i++)
#pragma unroll
        for (int j = 0; j < 8; j++) { tot[i][j] = 0.f; acc[i][j] = 0.f; }

#pragma unroll 1
    for (int k0 = 0; k0 < Ii; k0 += 8) {
        float4 av = make_float4(0.f, 0.f, 0.f, 0.f);
        if (k0 + aCol < Ii)  // Ii % 4 == 0 so a full float4 stays in-bounds
            av = *(const float4*)(A + (size_t)(row0 + aRow) * Ii + k0 + aCol);
        As[aCol + 0][aRow] = av.x;
        As[aCol + 1][aRow] = av.y;
        As[aCol + 2][aRow] = av.z;
        As[aCol + 3][aRow] = av.w;

        float4 bv = make_float4(0.f, 0.f, 0.f, 0.f);
        if (k0 + bRow < Ii)
            bv = *(const float4*)(W1 + (size_t)(k0 + bRow) * Nn + col0 + bCol);
        *(float4*)&Bs[bRow][bCol] = bv;
        __syncthreads();

#pragma unroll
        for (int k = 0; k < 8; k++) {
            float4 a0 = *(const float4*)&As[k][ty * 8];
            float4 a1 = *(const float4*)&As[k][ty * 8 + 4];
            float4 c0 = *(const float4*)&Bs[k][tx * 8];
            float4 c1 = *(const float4*)&Bs[k][tx * 8 + 4];
            float ra[8] = {a0.x, a0.y, a0.z, a0.w, a1.x, a1.y, a1.z, a1.w};
            float rb[8] = {c0.x, c0.y, c0.z, c0.w, c1.x, c1.y, c1.z, c1.w};
#pragma unroll
            for (int i = 0; i < 8; i++)
#pragma unroll
                for (int j = 0; j < 8; j++)
                    acc[i][j] = __fmaf_rn(ra[i], rb[j], acc[i][j]);
        }
        __syncthreads();

        if (((k0 + 8) % KC) == 0) {   // panel boundary at k=512: C += panel
#pragma unroll
            for (int i = 0; i < 8; i++)
#pragma unroll
                for (int j = 0; j < 8; j++) {
                    tot[i][j] = __fadd_rn(tot[i][j], acc[i][j]);
                    acc[i][j] = 0.f;
                }
        }
    }
    // final fold: C += tail panel [512,700)
#pragma unroll
    for (int i = 0; i < 8; i++)
#pragma unroll
        for (int j = 0; j < 8; j++)
            tot[i][j] = __fadd_rn(tot[i][j], acc[i][j]);

    float bias[8];
#pragma unroll
    for (int j = 0; j < 8; j++) bias[j] = b1[col0 + tx * 8 + j];

#pragma unroll
    for (int i = 0; i < 8; i++) {
        int r  = row0 + ty * 8 + i;
        int bi = r / Tt;
        int tt = r - bi * Tt;
        float* c = g_IN + ((size_t)tt * Bb + bi) * Nn + col0 + tx * 8;
#pragma unroll
        for (int j = 0; j < 8; j++)
            c[j] = __fadd_rn(tot[i][j], bias[j]);   // in_curr = dot + b1
    }
}

// ---------------------------------------------------------------------------
// rec_gemm: one 512-wide k-panel of REC = spk_prev @ V per CTA.
// DOUBLE-BUFFERED: prefetch tile kt+1 into registers while computing tile kt
// from smem buffer kt&1; ONE __syncthreads per tile. Arithmetic per output
// element is the identical ascending-k FMA chain (bit-exact vs R15).
// grid (32 n-tiles, 4 b-tiles, 4 panels) = 512 CTAs, 128 threads.
__global__ __launch_bounds__(128) void rec_gemm(int pp, const float* __restrict__ V) {
    __shared__ float As[2][8][64];   // [buf][kk][sample-row]
    __shared__ float Bs[2][8][64];   // [buf][kk][neuron-col]
    const int tid  = threadIdx.x;
    const int n0   = blockIdx.x * 64;
    const int b0   = blockIdx.y * 64;
    const int kbeg = blockIdx.z * KC;
    const float* __restrict__ S = g_spkf[pp];

    const int rg = tid >> 3;          // 0..15, rows rg*4..+3
    const int cg = tid & 7;           // 0..7,  cols cg*8..+7

    const int lr  = tid >> 1;         // 0..63 : A-load row
    const int lk4 = (tid & 1) * 4;    // 0 or 4: A-load k offset
    const int lkb = tid >> 4;         // 0..7  : B-load k row
    const int lc4 = (tid & 15) * 4;   // 0..60 : B-load col offset

    const float* __restrict__ aptr = S + (size_t)(b0 + lr) * Nn + kbeg + lk4;
    const float* __restrict__ bptr = V + (size_t)(kbeg + lkb) * Nn + n0 + lc4;

    float acc[4][8];
#pragma unroll
    for (int i = 0; i < 4; i++)
#pragma unroll
        for (int j = 0; j < 8; j++) acc[i][j] = 0.f;

    // preload tile 0
    float4 a  = *(const float4*)aptr;
    float4 v4 = *(const float4*)bptr;
    As[0][lk4 + 0][lr] = a.x;
    As[0][lk4 + 1][lr] = a.y;
    As[0][lk4 + 2][lr] = a.z;
    As[0][lk4 + 3][lr] = a.w;
    *(float4*)&Bs[0][lkb][lc4] = v4;
    __syncthreads();

    const int NT = KC / 8;   // 64 tiles
#pragma unroll 1
    for (int kt = 0; kt < NT; kt++) {
        const int cur = kt & 1;
        // prefetch next tile into registers (latency overlapped with FMAs)
        if (kt + 1 < NT) {
            a  = *(const float4*)(aptr + (kt + 1) * 8);
            v4 = *(const float4*)(bptr + (size_t)(kt + 1) * 8 * Nn);
        }

#pragma unroll
        for (int kk = 0; kk < 8; kk++) {
            float4 av  = *(const float4*)&As[cur][kk][rg * 4];
            float4 bv0 = *(const float4*)&Bs[cur][kk][cg * 8];
            float4 bv1 = *(const float4*)&Bs[cur][kk][cg * 8 + 4];
            float ra[4] = {av.x, av.y, av.z, av.w};
            float rb[8] = {bv0.x, bv0.y, bv0.z, bv0.w, bv1.x, bv1.y, bv1.z, bv1.w};
#pragma unroll
            for (int i = 0; i < 4; i++)
#pragma unroll
                for (int j = 0; j < 8; j++)
                    acc[i][j] = __fmaf_rn(ra[i], rb[j], acc[i][j]);
        }

        if (kt + 1 < NT) {
            const int nxt = cur ^ 1;
            As[nxt][lk4 + 0][lr] = a.x;
            As[nxt][lk4 + 1][lr] = a.y;
            As[nxt][lk4 + 2][lr] = a.z;
            As[nxt][lk4 + 3][lr] = a.w;
            *(float4*)&Bs[nxt][lkb][lc4] = v4;
        }
        __syncthreads();
    }

    float* __restrict__ P = g_part + (size_t)blockIdx.z * (Bb * Nn);
#pragma unroll
    for (int i = 0; i < 4; i++) {
        size_t base = (size_t)(b0 + rg * 4 + i) * Nn + n0 + cg * 8;
        *(float4*)(P + base)     = make_float4(acc[i][0], acc[i][1], acc[i][2], acc[i][3]);
        *(float4*)(P + base + 4) = make_float4(acc[i][4], acc[i][5], acc[i][6], acc[i][7]);
    }
}

// ---------------------------------------------------------------------------
// rec_update: fold panel partials in ASCENDING order (tot=0; tot+=P0..P3 —
// identical rounded adds to the fused fold), then CONTRACTED RLeaky update:
//   m' = ((fma(0.9, m, ic) + rec) + bV) - reset
// One float4 per thread; grid 512 x 256 covers Bb*Nn.
__global__ __launch_bounds__(256) void rec_update(int t, int pp,
                                                  const float* __restrict__ bV) {
    const size_t e = ((size_t)blockIdx.x * 256 + threadIdx.x) * 4;
    const int n = (int)(e & (Nn - 1));
    const float4 p0 = *(const float4*)(g_part + e);
    const float4 p1 = *(const float4*)(g_part + (size_t)(Bb * Nn) + e);
    const float4 p2 = *(const float4*)(g_part + 2 * (size_t)(Bb * Nn) + e);
    const float4 p3 = *(const float4*)(g_part + 3 * (size_t)(Bb * Nn) + e);
    float4 m4 = *(float4*)(g_mem + e);
    const float4 ic = *(const float4*)(g_IN + (size_t)t * Bb * Nn + e);
    const float4 bv = *(const float4*)(bV + n);
    float4 s4;

#define REC_UP(c)                                                              \
    {                                                                          \
        float tot = 0.f;                                                       \
        tot = __fadd_rn(tot, p0.c);                                            \
        tot = __fadd_rn(tot, p1.c);                                            \
        tot = __fadd_rn(tot, p2.c);                                            \
        tot = __fadd_rn(tot, p3.c);                                            \
        float m = m4.c;                                                        \
        float r = (m > 1.0f) ? 1.0f : 0.0f;                                    \
        m = __fmaf_rn(0.9f, m, ic.c);                                          \
        m = __fadd_rn(m, tot);                                                 \
        m = __fadd_rn(m, bv.c);                                                \
        m = __fsub_rn(m, r);                                                   \
        m4.c = m;                                                              \
        s4.c = (m > 1.0f) ? 1.0f : 0.0f;                                       \
    }
    REC_UP(x) REC_UP(y) REC_UP(z) REC_UP(w)
#undef REC_UP

    *(float4*)(g_mem + e) = m4;
    *(float4*)(g_spkf[pp ^ 1] + e) = s4;
}

// ---------------------------------------------------------------------------
// out_step: panel-parallel. Warp s owns k-panel [s*512,(s+1)*512): lane o
// runs the ascending FMA chain (sp[k] warp-uniform broadcast, W2 coalesced).
// Panels folded in ascending order via smem — identical rounding to fused.
// Then oc = dot + b2, CONTRACTED LIF, outputs.
__global__ __launch_bounds__(128) void out_step(int t, int pc,
                                                const float* __restrict__ W2,
                                                const float* __restrict__ b2,
                                                float* __restrict__ out) {
    __shared__ float sred[4][32];
    const int b = blockIdx.x;
    const int s = threadIdx.x >> 5;   // panel = warp id
    const int o = threadIdx.x & 31;

    float p = 0.f;
    if (o < Oo) {
        const float* __restrict__ sp = g_spkf[pc] + (size_t)b * Nn + s * KC;
        const float* __restrict__ w  = W2 + (size_t)(s * KC) * Oo + o;
#pragma unroll 8
        for (int k = 0; k < KC; k++)
            p = __fmaf_rn(sp[k], w[(size_t)k * Oo], p);
    }
    sred[s][o] = p;
    __syncthreads();

    if (threadIdx.x < 32 && o < Oo) {
        float tot = 0.f;
        tot = __fadd_rn(tot, sred[0][o]);
        tot = __fadd_rn(tot, sred[1][o]);
        tot = __fadd_rn(tot, sred[2][o]);
        tot = __fadd_rn(tot, sred[3][o]);

        float oc = __fadd_rn(tot, b2[o]);
        float m  = g_memout[b * Oo + o];
        float r  = (m > 1.0f) ? 1.0f : 0.0f;
        m = __fmaf_rn(0.8f, m, oc);                  // fma: beta*mem + out_curr
        m = __fsub_rn(m, r);
        g_memout[b * Oo + o] = m;

        float sp_v = (m > 1.0f) ? 1.0f : 0.0f;
        size_t o1 = ((size_t)t * Bb + b) * Oo + o;
        out[o1] = sp_v;                                // spk_rec
        out[(size_t)Tt * Bb * Oo + o1] = m;            // mem_rec
    }
}

// ---------------------------------------------------------------------------
extern "C" void kernel_launch(void* const* d_in, const int* in_sizes, int n_in,
                              void* d_out, int out_size) {
    const float* data = (const float*)d_in[0];  // [B,T,I]
    const float* W1   = (const float*)d_in[1];  // [I,N]
    const float* b1   = (const float*)d_in[2];  // [N]
    const float* V    = (const float*)d_in[3];  // [N,N]
    const float* bV   = (const float*)d_in[4];  // [N]
    const float* W2   = (const float*)d_in[5];  // [N,O]
    const float* b2   = (const float*)d_in[6];  // [O]
    float* out = (float*)d_out;

    zero_init<<<256, 256>>>();

    dim3 g1(Nn / 128, (Bb * Tt) / 128);  // (16, 500)
    gemm1<<<g1, 256>>>(data, W1, b1);

    for (int t = 0; t < Tt; ++t) {
        int pp = t & 1;
        rec_gemm<<<dim3(Nn / 64, Bb / 64, 4), 128>>>(pp, V);
        rec_update<<<512, 256>>>(t, pp, bV);
        out_step<<<Bb, 128>>>(t, pp ^ 1, W2, b2, out);
    }
}